// round 8
// baseline (speedup 1.0000x reference)
#include <cuda_runtime.h>
#include <math.h>

#define BDIM   512
#define STAGES 3
#define MAXG   4096

// Scratch (allocation-free): per-CTA partial {loss_sum, keep_count}.
__device__ float2       g_part[MAXG];
__device__ unsigned int g_done = 0;

__device__ __forceinline__ float warp_sum(float v) {
#pragma unroll
    for (int o = 16; o > 0; o >>= 1)
        v += __shfl_xor_sync(0xffffffffu, v, o);
    return v;
}

__device__ __forceinline__ unsigned int smem_u32(const void* p) {
    return (unsigned int)__cvta_generic_to_shared(p);
}
__device__ __forceinline__ void mbar_init(unsigned int mb, unsigned int cnt) {
    asm volatile("mbarrier.init.shared.b64 [%0], %1;" :: "r"(mb), "r"(cnt) : "memory");
}
__device__ __forceinline__ void mbar_expect_tx(unsigned int mb, unsigned int bytes) {
    asm volatile("mbarrier.arrive.expect_tx.shared.b64 _, [%0], %1;"
                 :: "r"(mb), "r"(bytes) : "memory");
}
__device__ __forceinline__ void bulk_g2s(unsigned int dst, const void* src,
                                         unsigned int bytes, unsigned int mb) {
    asm volatile(
        "cp.async.bulk.shared::cta.global.mbarrier::complete_tx::bytes [%0], [%1], %2, [%3];"
        :: "r"(dst), "l"(src), "r"(bytes), "r"(mb) : "memory");
}
__device__ __forceinline__ void mbar_wait(unsigned int mb, unsigned int parity) {
    asm volatile(
        "{\n\t"
        ".reg .pred P;\n\t"
        "WAIT_%=:\n\t"
        "mbarrier.try_wait.parity.acquire.cta.shared::cta.b64 P, [%0], %1, 0x989680;\n\t"
        "@P bra.uni DONE_%=;\n\t"
        "bra.uni WAIT_%=;\n\t"
        "DONE_%=:\n\t"
        "}"
        :: "r"(mb), "r"(parity) : "memory");
}

// Persistent 512-thread CTA (1/SM), 3 stages x 2 rows (64KB bulk copies).
// One mbar wait + one barrier + one reduce round per TWO rows.
template <int NL>
__global__ void __launch_bounds__(BDIM, 1)
pers_kernel(const float* __restrict__ prd, const int* __restrict__ tgt,
            float* __restrict__ out, int xc, int B, int G)
{
    constexpr int ROW_BYTES   = NL * 4;         // 32768
    constexpr int ROW_F4      = NL / 4;         // 2048 float4
    constexpr int STAGE_F4    = 2 * ROW_F4;     // 2 rows per stage

    extern __shared__ float4 stage[];           // STAGES * STAGE_F4

    __shared__ __align__(8) unsigned long long mbar_store[STAGES];
    __shared__ float sh[2][4][BDIM / 32];       // [parity][{z0,z1,sel0,sel1}][warp]
    __shared__ int   shn[2][2][BDIM / 32];      // [parity][row][warp] hit counts
    __shared__ int   s_nl[2][2];                // [parity][row] num_listed
    __shared__ int   s_last;

    const int tid = threadIdx.x;
    const int w   = tid >> 5;
    const int l   = tid & 31;
    const int X   = xc - 1;
    const int bid = blockIdx.x;

    // row range for this CTA
    const int per   = B / G;
    const int rem   = B % G;
    const int start = bid * per + (bid < rem ? bid : rem);
    const int cnt   = per + (bid < rem ? 1 : 0);
    const int iters = (cnt + 1) >> 1;

    unsigned int mb[STAGES];
#pragma unroll
    for (int s = 0; s < STAGES; s++) mb[s] = smem_u32(&mbar_store[s]);

    if (tid == 0) {
#pragma unroll
        for (int s = 0; s < STAGES; s++) mbar_init(mb[s], 1);
    }
    __syncthreads();

    // initial prefetch: iterations 0..STAGES-1 (2 rows each)
    if (tid == 0) {
#pragma unroll
        for (int j = 0; j < STAGES; j++) {
            int r0 = 2 * j;
            if (r0 < cnt) {
                unsigned int bytes = (r0 + 1 < cnt) ? 2 * ROW_BYTES : ROW_BYTES;
                mbar_expect_tx(mb[j], bytes);
                bulk_g2s(smem_u32(stage + j * STAGE_F4),
                         prd + (size_t)(start + r0) * NL, bytes, mb[j]);
            }
        }
    }

    // labels for iteration 0: threads [0,50] -> row0, [64,114] -> row1
    int labv = 0;
    if (cnt > 0 && tid <= X)                       labv = tgt[(size_t)start * xc + tid];
    if (cnt > 1 && tid >= 64 && tid <= 64 + X)     labv = tgt[(size_t)(start + 1) * xc + (tid - 64)];

    float acc_loss = 0.0f;   // thread 0 only
    float acc_keep = 0.0f;

    int s = 0, ph = 0, wraps = 0;
    for (int i = 0; i < iters; i++) {
        const int  r0    = 2 * i;
        const bool has2  = (r0 + 1) < cnt;
        const int  par   = i & 1;

        mbar_wait(mb[s], ph);

        // prefetch next iteration's labels (hides under exp phase)
        int labn = 0;
        {
            int nr = r0 + 2;
            if (nr < cnt && tid <= X)
                labn = tgt[(size_t)(start + nr) * xc + tid];
            if (nr + 1 < cnt && tid >= 64 && tid <= 64 + X)
                labn = tgt[(size_t)(start + nr + 1) * xc + (tid - 64)];
        }

        const float4* row0 = stage + s * STAGE_F4;
        const float4* row1 = row0 + ROW_F4;
        const float*  r0f  = (const float*)row0;
        const float*  r1f  = (const float*)row1;

        // exp-sum both rows from smem (4 LDS.128 + 16 exp per row per thread)
        float lsum0 = 0.0f, lsum1 = 0.0f;
#pragma unroll
        for (int k = 0; k < 4; k++) {
            float4 v = row0[tid + k * BDIM];
            lsum0 += __expf(v.x); lsum0 += __expf(v.y);
            lsum0 += __expf(v.z); lsum0 += __expf(v.w);
        }
        if (has2) {
#pragma unroll
            for (int k = 0; k < 4; k++) {
                float4 v = row1[tid + k * BDIM];
                lsum1 += __expf(v.x); lsum1 += __expf(v.y);
                lsum1 += __expf(v.z); lsum1 += __expf(v.w);
            }
        }

        // label gathers straight from smem
        bool hit0 = (tid < X) && (labv != 0);
        bool hit1 = has2 && (tid >= 64) && (tid < 64 + X) && (labv != 0);
        float sel0 = hit0 ? __expf(r0f[labv]) : 0.0f;
        float sel1 = hit1 ? __expf(r1f[labv]) : 0.0f;
        if (tid == X)      s_nl[par][0] = labv;
        if (tid == 64 + X) s_nl[par][1] = labv;

        // per-iteration block reduction (4 float sums + 2 popc counts)
        float a0 = warp_sum(lsum0);
        float a1 = warp_sum(lsum1);
        float b0 = warp_sum(sel0);
        float b1 = warp_sum(sel1);
        unsigned int bal0 = __ballot_sync(0xffffffffu, hit0);
        unsigned int bal1 = __ballot_sync(0xffffffffu, hit1);
        if (l == 0) {
            sh[par][0][w] = a0; sh[par][1][w] = a1;
            sh[par][2][w] = b0; sh[par][3][w] = b1;
            shn[par][0][w] = __popc(bal0);
            shn[par][1][w] = __popc(bal1);
        }
        __syncthreads();   // all reads of stage s complete past this point

        // refill stage s with iteration i+STAGES
        if (tid == 0) {
            int nr0 = 2 * (i + STAGES);
            if (nr0 < cnt) {
                unsigned int bytes = (nr0 + 1 < cnt) ? 2 * ROW_BYTES : ROW_BYTES;
                mbar_expect_tx(mb[s], bytes);
                bulk_g2s(smem_u32(stage + s * STAGE_F4),
                         prd + (size_t)(start + nr0) * NL, bytes, mb[s]);
            }
        }

        if (tid < 32) {
            const int NW = BDIM / 32;
            float z0 = (tid < NW) ? sh[par][0][tid] : 0.0f;
            float z1 = (tid < NW) ? sh[par][1][tid] : 0.0f;
            float y0 = (tid < NW) ? sh[par][2][tid] : 0.0f;
            float y1 = (tid < NW) ? sh[par][3][tid] : 0.0f;
            int   n0 = (tid < NW) ? shn[par][0][tid] : 0;
            int   n1 = (tid < NW) ? shn[par][1][tid] : 0;
            z0 = warp_sum(z0); z1 = warp_sum(z1);
            y0 = warp_sum(y0); y1 = warp_sum(y1);
#pragma unroll
            for (int o = 16; o > 0; o >>= 1) {
                n0 += __shfl_xor_sync(0xffffffffu, n0, o);
                n1 += __shfl_xor_sync(0xffffffffu, n1, o);
            }
            if (tid == 0) {
                bool k0 = (s_nl[par][0] - (X - n0)) > 0;
                if (k0) {
                    acc_loss += -__logf(y0 / z0 + 1e-5f);
                    acc_keep += 1.0f;
                }
                if (has2) {
                    bool k1 = (s_nl[par][1] - (X - n1)) > 0;
                    if (k1) {
                        acc_loss += -__logf(y1 / z1 + 1e-5f);
                        acc_keep += 1.0f;
                    }
                }
            }
        }

        labv = labn;
        if (++s == STAGES) { s = 0; wraps ^= 1; }
        ph = wraps;
    }

    // ---- one global write per CTA, then last-CTA tiny reduce ----
    if (tid == 0) {
        g_part[bid] = make_float2(acc_loss, acc_keep);
        __threadfence();
        unsigned int n = atomicAdd(&g_done, 1u);
        s_last = (n == (unsigned int)(G - 1)) ? 1 : 0;
    }
    __syncthreads();
    if (!s_last) return;
    __threadfence();   // acquire

    float ssum = 0.0f, csum = 0.0f;
    for (int i = tid; i < G; i += BDIM) {
        float2 v = g_part[i];
        ssum += v.x;
        csum += v.y;
    }
    ssum = warp_sum(ssum);
    csum = warp_sum(csum);
    __syncthreads();
    if (l == 0) { sh[0][0][w] = ssum; sh[0][1][w] = csum; }
    __syncthreads();
    if (tid < 32) {
        float x  = (tid < BDIM / 32) ? sh[0][0][tid] : 0.0f;
        float cc = (tid < BDIM / 32) ? sh[0][1][tid] : 0.0f;
        x  = warp_sum(x);
        cc = warp_sum(cc);
        if (tid == 0) {
            out[0] = x / fmaxf(cc, 1.0f);
            g_done = 0;                      // reset for next graph replay
        }
    }
}

// Generic fallback (any nlabels).
__device__ float2 g_row_fb[65536];
__global__ void __launch_bounds__(256)
fused_generic(const float* __restrict__ prd, const int* __restrict__ tgt,
              float* __restrict__ out, int nlabels, int xc, int B)
{
    __shared__ float shf[8];
    __shared__ float shs[8];
    __shared__ float shc[8];
    __shared__ int   s_last;

    const int row = blockIdx.x;
    const int tid = threadIdx.x;
    const int w   = tid >> 5;
    const int l   = tid & 31;

    const float* p    = prd + (size_t)row * nlabels;
    const int*   trow = tgt + (size_t)row * xc;
    const int    X    = xc - 1;

    float lsum = 0.0f;
    for (int i = tid; i < nlabels; i += 256) lsum += __expf(p[i]);

    float sel = 0.0f, nzf = 0.0f;
    for (int j = tid; j < X; j += 256) {
        int lab = trow[j];
        if (lab != 0) { sel += __expf(p[lab]); nzf += 1.0f; }
    }

    float a = warp_sum(lsum), b = warp_sum(sel), c = warp_sum(nzf);
    if (l == 0) { shf[w] = a; shs[w] = b; shc[w] = c; }
    __syncthreads();
    if (tid < 32) {
        float x  = (tid < 8) ? shf[tid] : 0.0f;
        float y  = (tid < 8) ? shs[tid] : 0.0f;
        float cc = (tid < 8) ? shc[tid] : 0.0f;
        x = warp_sum(x); y = warp_sum(y); cc = warp_sum(cc);
        if (tid == 0) {
            int num_listed = trow[X];
            int ignored    = X - (int)(cc + 0.5f);
            bool keep      = (num_listed - ignored) > 0;
            float per      = -__logf(y / x + 1e-5f);
            g_row_fb[row] = make_float2(keep ? per : 0.0f, keep ? 1.0f : 0.0f);
        }
    }
    if (tid == 0) {
        __threadfence();
        unsigned int n = atomicAdd(&g_done, 1u);
        s_last = (n == (unsigned int)(gridDim.x - 1)) ? 1 : 0;
    }
    __syncthreads();
    if (!s_last) return;
    __threadfence();

    float s = 0.0f, c2 = 0.0f;
    for (int i = tid; i < B; i += 256) {
        float2 v = g_row_fb[i];
        s += v.x; c2 += v.y;
    }
    s = warp_sum(s); c2 = warp_sum(c2);
    __syncthreads();
    if (l == 0) { shf[w] = s; shs[w] = c2; }
    __syncthreads();
    if (tid < 32) {
        float x  = (tid < 8) ? shf[tid] : 0.0f;
        float cc = (tid < 8) ? shs[tid] : 0.0f;
        x = warp_sum(x); cc = warp_sum(cc);
        if (tid == 0) { out[0] = x / fmaxf(cc, 1.0f); g_done = 0; }
    }
}

extern "C" void kernel_launch(void* const* d_in, const int* in_sizes, int n_in,
                              void* d_out, int out_size)
{
    const float* prd = (const float*)d_in[0];
    const int*   tgt = (const int*)d_in[1];

    const int xc = 51;                               // X=50 labels + count col
    const int B  = in_sizes[1] / xc;
    const int nlabels = (int)((long long)in_sizes[0] / B);

    if (nlabels == 8192) {
        int sms = 148;
        cudaDeviceGetAttribute(&sms, cudaDevAttrMultiProcessorCount, 0);
        int G = sms;                                 // 1 persistent CTA per SM
        if (G > B)    G = B;
        if (G > MAXG) G = MAXG;
        size_t dyn = (size_t)STAGES * 2 * 8192 * sizeof(float);   // 192 KB
        cudaFuncSetAttribute(pers_kernel<8192>,
                             cudaFuncAttributeMaxDynamicSharedMemorySize, (int)dyn);
        pers_kernel<8192><<<G, BDIM, dyn>>>(prd, tgt, (float*)d_out, xc, B, G);
    } else {
        fused_generic<<<B, 256>>>(prd, tgt, (float*)d_out, nlabels, xc, B);
    }
}

// round 9
// speedup vs baseline: 1.0079x; 1.0079x over previous
#include <cuda_runtime.h>
#include <math.h>

#define BDIM   256
#define NWARP  (BDIM / 32)
#define STAGES 3
#define SLOTS  4
#define MAXG   4096

// Scratch (allocation-free): per-CTA partial {loss_sum, keep_count}.
__device__ float2       g_part[MAXG];
__device__ unsigned int g_done = 0;

__device__ __forceinline__ float warp_sum(float v) {
#pragma unroll
    for (int o = 16; o > 0; o >>= 1)
        v += __shfl_xor_sync(0xffffffffu, v, o);
    return v;
}

__device__ __forceinline__ unsigned int smem_u32(const void* p) {
    return (unsigned int)__cvta_generic_to_shared(p);
}
__device__ __forceinline__ void mbar_init(unsigned int mb, unsigned int cnt) {
    asm volatile("mbarrier.init.shared.b64 [%0], %1;" :: "r"(mb), "r"(cnt) : "memory");
}
__device__ __forceinline__ void mbar_arrive(unsigned int mb) {
    asm volatile("mbarrier.arrive.release.cta.shared::cta.b64 _, [%0];"
                 :: "r"(mb) : "memory");
}
__device__ __forceinline__ void mbar_expect_tx(unsigned int mb, unsigned int bytes) {
    asm volatile("mbarrier.arrive.expect_tx.shared.b64 _, [%0], %1;"
                 :: "r"(mb), "r"(bytes) : "memory");
}
__device__ __forceinline__ void bulk_g2s(unsigned int dst, const void* src,
                                         unsigned int bytes, unsigned int mb) {
    asm volatile(
        "cp.async.bulk.shared::cta.global.mbarrier::complete_tx::bytes [%0], [%1], %2, [%3];"
        :: "r"(dst), "l"(src), "r"(bytes), "r"(mb) : "memory");
}
__device__ __forceinline__ void mbar_wait(unsigned int mb, unsigned int parity) {
    asm volatile(
        "{\n\t"
        ".reg .pred P;\n\t"
        "WAIT_%=:\n\t"
        "mbarrier.try_wait.parity.acquire.cta.shared::cta.b64 P, [%0], %1, 0x989680;\n\t"
        "@P bra.uni DONE_%=;\n\t"
        "bra.uni WAIT_%=;\n\t"
        "DONE_%=:\n\t"
        "}"
        :: "r"(mb), "r"(parity) : "memory");
}

// Persistent 256-thread CTA (2/SM), 3 x 32KB stages, WARP-DECOUPLED:
// no per-row __syncthreads; warps free-run up to stage depth via per-stage
// empty mbarriers; warp 0 finalizes rows via 4-deep partial mbarriers.
template <int NL>
__global__ void __launch_bounds__(BDIM, 2)
pers_kernel(const float* __restrict__ prd, const int* __restrict__ tgt,
            float* __restrict__ out, int xc, int B, int G)
{
    constexpr int ROW_BYTES = NL * 4;          // 32768
    constexpr int ROW_F4    = NL / 4;          // 2048 float4

    extern __shared__ float4 stage[];          // STAGES * ROW_F4

    __shared__ __align__(8) unsigned long long mb_full_s[STAGES];
    __shared__ __align__(8) unsigned long long mb_empty_s[STAGES];
    __shared__ __align__(8) unsigned long long mb_part_s[SLOTS];
    __shared__ float sh[SLOTS][2][NWARP];      // [slot][{z,sel}][warp]
    __shared__ int   shn[SLOTS][NWARP];        // [slot][warp] hit counts
    __shared__ int   s_nl[SLOTS];              // [slot] num_listed
    __shared__ int   s_last;

    const int tid = threadIdx.x;
    const int w   = tid >> 5;
    const int l   = tid & 31;
    const int X   = xc - 1;
    const int wX  = X >> 5;                    // warp holding thread X
    const int lX  = X & 31;
    const int bid = blockIdx.x;

    // row range for this CTA
    const int per   = B / G;
    const int rem   = B % G;
    const int start = bid * per + (bid < rem ? bid : rem);
    const int cnt   = per + (bid < rem ? 1 : 0);

    unsigned int mfull[STAGES], mempty[STAGES], mpart[SLOTS];
#pragma unroll
    for (int s = 0; s < STAGES; s++) {
        mfull[s]  = smem_u32(&mb_full_s[s]);
        mempty[s] = smem_u32(&mb_empty_s[s]);
    }
#pragma unroll
    for (int p = 0; p < SLOTS; p++) mpart[p] = smem_u32(&mb_part_s[p]);

    if (tid == 0) {
#pragma unroll
        for (int s = 0; s < STAGES; s++) {
            mbar_init(mfull[s], 1);            // tx-based completion
            mbar_init(mempty[s], NWARP);       // one arrive per warp
        }
#pragma unroll
        for (int p = 0; p < SLOTS; p++) mbar_init(mpart[p], NWARP);
    }
    __syncthreads();

    // initial prefetch: rows start..start+STAGES-1
    if (tid == 0) {
#pragma unroll
        for (int j = 0; j < STAGES; j++) {
            if (j < cnt) {
                mbar_expect_tx(mfull[j], ROW_BYTES);
                bulk_g2s(smem_u32(stage + j * ROW_F4),
                         prd + (size_t)(start + j) * NL, ROW_BYTES, mfull[j]);
            }
        }
    }

    // labels for row 0 (prefetched one row ahead thereafter)
    int labv = 0;
    if (tid <= X && cnt > 0) labv = tgt[(size_t)start * xc + tid];

    float acc_loss = 0.0f;   // warp0 lane0 only
    float acc_keep = 0.0f;

    int s = 0, ph = 0;       // stage index + full/empty parity: (i/3)&1
    int pph = 0;             // partial parity: (i/4)&1

    for (int i = 0; i < cnt; i++) {
        const int slot = i & 3;

        mbar_wait(mfull[s], ph);

        // prefetch next row's labels (warps 0/1 only; hides under exp)
        int labn = 0;
        if (tid <= X && (i + 1) < cnt)
            labn = tgt[(size_t)(start + i + 1) * xc + tid];

        const float4* rowp = stage + s * ROW_F4;
        const float*  rowf = (const float*)rowp;

        // slice compute: 8 LDS.128 + 32 exp
        float lsum = 0.0f;
#pragma unroll
        for (int k = 0; k < 8; k++) {
            float4 v = rowp[tid + k * BDIM];
            lsum += __expf(v.x); lsum += __expf(v.y);
            lsum += __expf(v.z); lsum += __expf(v.w);
        }

        // label gather from smem (whole row resident)
        bool  hit = (tid < X) && (labv != 0);
        float sel = hit ? __expf(rowf[labv]) : 0.0f;

        // warp-local reductions (r0/r1 data-depend on every stage read ->
        // lane0's arrives below are safely ordered after all loads)
        float r0 = warp_sum(lsum);
        float r1 = warp_sum(sel);
        unsigned int bal = __ballot_sync(0xffffffffu, hit);

        // route num_listed (thread X's labv) to lane0 of warp wX, store
        if (w == wX) {
            int nlv = __shfl_sync(0xffffffffu, labv, lX);
            if (l == 0) s_nl[slot] = nlv;
        }

        if (l == 0) {
            sh[slot][0][w] = r0;
            sh[slot][1][w] = r1;
            shn[slot][w]   = __popc(bal);
            mbar_arrive(mpart[slot]);          // publish partials (release)
            mbar_arrive(mempty[s]);            // stage slice consumed
        }

        if (w == 0) {
            // refill stage s with row i+STAGES once all warps consumed it
            if (l == 0 && (i + STAGES) < cnt) {
                mbar_wait(mempty[s], ph);
                mbar_expect_tx(mfull[s], ROW_BYTES);
                bulk_g2s(smem_u32(stage + s * ROW_F4),
                         prd + (size_t)(start + i + STAGES) * NL,
                         ROW_BYTES, mfull[s]);
            }
            // finalize row i
            mbar_wait(mpart[slot], pph);
            float z = (l < NWARP) ? sh[slot][0][l] : 0.0f;
            float y = (l < NWARP) ? sh[slot][1][l] : 0.0f;
            int   n = (l < NWARP) ? shn[slot][l]   : 0;
            z = warp_sum(z);
            y = warp_sum(y);
#pragma unroll
            for (int o = 16; o > 0; o >>= 1)
                n += __shfl_xor_sync(0xffffffffu, n, o);
            if (l == 0) {
                bool keep = (s_nl[slot] - (X - n)) > 0;
                if (keep) {
                    acc_loss += -__logf(y / z + 1e-5f);
                    acc_keep += 1.0f;
                }
            }
        }

        labv = labn;
        if (++s == STAGES) { s = 0; ph ^= 1; }
        if (slot == 3) pph ^= 1;
    }

    __syncthreads();   // rejoin all warps

    // ---- one global write per CTA, then last-CTA tiny reduce ----
    if (tid == 0) {
        g_part[bid] = make_float2(acc_loss, acc_keep);
        __threadfence();
        unsigned int n = atomicAdd(&g_done, 1u);
        s_last = (n == (unsigned int)(G - 1)) ? 1 : 0;
    }
    __syncthreads();
    if (!s_last) return;
    __threadfence();   // acquire

    float ssum = 0.0f, csum = 0.0f;
    for (int i = tid; i < G; i += BDIM) {
        float2 v = g_part[i];
        ssum += v.x;
        csum += v.y;
    }
    ssum = warp_sum(ssum);
    csum = warp_sum(csum);
    __syncthreads();
    if (l == 0) { sh[0][0][w] = ssum; sh[1][0][w] = csum; }
    __syncthreads();
    if (tid < 32) {
        float x  = (tid < NWARP) ? sh[0][0][tid] : 0.0f;
        float cc = (tid < NWARP) ? sh[1][0][tid] : 0.0f;
        x  = warp_sum(x);
        cc = warp_sum(cc);
        if (tid == 0) {
            out[0] = x / fmaxf(cc, 1.0f);
            g_done = 0;                      // reset for next graph replay
        }
    }
}

// Generic fallback (any nlabels).
__device__ float2 g_row_fb[65536];
__global__ void __launch_bounds__(256)
fused_generic(const float* __restrict__ prd, const int* __restrict__ tgt,
              float* __restrict__ out, int nlabels, int xc, int B)
{
    __shared__ float shf[8];
    __shared__ float shs[8];
    __shared__ float shc[8];
    __shared__ int   s_last;

    const int row = blockIdx.x;
    const int tid = threadIdx.x;
    const int w   = tid >> 5;
    const int l   = tid & 31;

    const float* p    = prd + (size_t)row * nlabels;
    const int*   trow = tgt + (size_t)row * xc;
    const int    X    = xc - 1;

    float lsum = 0.0f;
    for (int i = tid; i < nlabels; i += 256) lsum += __expf(p[i]);

    float sel = 0.0f, nzf = 0.0f;
    for (int j = tid; j < X; j += 256) {
        int lab = trow[j];
        if (lab != 0) { sel += __expf(p[lab]); nzf += 1.0f; }
    }

    float a = warp_sum(lsum), b = warp_sum(sel), c = warp_sum(nzf);
    if (l == 0) { shf[w] = a; shs[w] = b; shc[w] = c; }
    __syncthreads();
    if (tid < 32) {
        float x  = (tid < 8) ? shf[tid] : 0.0f;
        float y  = (tid < 8) ? shs[tid] : 0.0f;
        float cc = (tid < 8) ? shc[tid] : 0.0f;
        x = warp_sum(x); y = warp_sum(y); cc = warp_sum(cc);
        if (tid == 0) {
            int num_listed = trow[X];
            int ignored    = X - (int)(cc + 0.5f);
            bool keep      = (num_listed - ignored) > 0;
            float per      = -__logf(y / x + 1e-5f);
            g_row_fb[row] = make_float2(keep ? per : 0.0f, keep ? 1.0f : 0.0f);
        }
    }
    if (tid == 0) {
        __threadfence();
        unsigned int n = atomicAdd(&g_done, 1u);
        s_last = (n == (unsigned int)(gridDim.x - 1)) ? 1 : 0;
    }
    __syncthreads();
    if (!s_last) return;
    __threadfence();

    float s = 0.0f, c2 = 0.0f;
    for (int i = tid; i < B; i += 256) {
        float2 v = g_row_fb[i];
        s += v.x; c2 += v.y;
    }
    s = warp_sum(s); c2 = warp_sum(c2);
    __syncthreads();
    if (l == 0) { shf[w] = s; shs[w] = c2; }
    __syncthreads();
    if (tid < 32) {
        float x  = (tid < 8) ? shf[tid] : 0.0f;
        float cc = (tid < 8) ? shs[tid] : 0.0f;
        x = warp_sum(x); cc = warp_sum(cc);
        if (tid == 0) { out[0] = x / fmaxf(cc, 1.0f); g_done = 0; }
    }
}

extern "C" void kernel_launch(void* const* d_in, const int* in_sizes, int n_in,
                              void* d_out, int out_size)
{
    const float* prd = (const float*)d_in[0];
    const int*   tgt = (const int*)d_in[1];

    const int xc = 51;                               // X=50 labels + count col
    const int B  = in_sizes[1] / xc;
    const int nlabels = (int)((long long)in_sizes[0] / B);

    if (nlabels == 8192) {
        int sms = 148;
        cudaDeviceGetAttribute(&sms, cudaDevAttrMultiProcessorCount, 0);
        int G = 2 * sms;                             // 2 persistent CTAs per SM
        if (G > B)    G = B;
        if (G > MAXG) G = MAXG;
        size_t dyn = (size_t)STAGES * 8192 * sizeof(float);   // 96 KB per CTA
        cudaFuncSetAttribute(pers_kernel<8192>,
                             cudaFuncAttributeMaxDynamicSharedMemorySize, (int)dyn);
        pers_kernel<8192><<<G, BDIM, dyn>>>(prd, tgt, (float*)d_out, xc, B, G);
    } else {
        fused_generic<<<B, 256>>>(prd, tgt, (float*)d_out, nlabels, xc, B);
    }
}

// round 10
// speedup vs baseline: 1.0195x; 1.0116x over previous
#include <cuda_runtime.h>
#include <math.h>

#define BDIM   256
#define STAGES 3
#define MAXG   4096

// Scratch (allocation-free): per-CTA partial {loss_sum, keep_count}.
__device__ float2       g_part[MAXG];
__device__ unsigned int g_done = 0;

__device__ __forceinline__ float warp_sum(float v) {
#pragma unroll
    for (int o = 16; o > 0; o >>= 1)
        v += __shfl_xor_sync(0xffffffffu, v, o);
    return v;
}

__device__ __forceinline__ unsigned int smem_u32(const void* p) {
    return (unsigned int)__cvta_generic_to_shared(p);
}
__device__ __forceinline__ void mbar_init(unsigned int mb, unsigned int cnt) {
    asm volatile("mbarrier.init.shared.b64 [%0], %1;" :: "r"(mb), "r"(cnt) : "memory");
}
__device__ __forceinline__ void mbar_expect_tx(unsigned int mb, unsigned int bytes) {
    asm volatile("mbarrier.arrive.expect_tx.shared.b64 _, [%0], %1;"
                 :: "r"(mb), "r"(bytes) : "memory");
}
// bulk copy with L2 evict_first policy (pure streaming data, no reuse)
__device__ __forceinline__ void bulk_g2s_ef(unsigned int dst, const void* src,
                                            unsigned int bytes, unsigned int mb) {
    asm volatile(
        "{\n\t"
        ".reg .b64 pol;\n\t"
        "createpolicy.fractional.L2::evict_first.b64 pol, 1.0;\n\t"
        "cp.async.bulk.shared::cta.global.mbarrier::complete_tx::bytes.L2::cache_hint"
        " [%0], [%1], %2, [%3], pol;\n\t"
        "}"
        :: "r"(dst), "l"(src), "r"(bytes), "r"(mb) : "memory");
}
__device__ __forceinline__ void mbar_wait(unsigned int mb, unsigned int parity) {
    asm volatile(
        "{\n\t"
        ".reg .pred P;\n\t"
        "WAIT_%=:\n\t"
        "mbarrier.try_wait.parity.acquire.cta.shared::cta.b64 P, [%0], %1, 0x989680;\n\t"
        "@P bra.uni DONE_%=;\n\t"
        "bra.uni WAIT_%=;\n\t"
        "DONE_%=:\n\t"
        "}"
        :: "r"(mb), "r"(parity) : "memory");
}

// sum of exp over a float4 using packed f32x2 range reduction + ex2.approx.
__device__ __forceinline__ float exp_sum4(float4 v) {
    const unsigned long long L2E2 = 0x3FB8AA3B3FB8AA3BULL;  // {log2e, log2e}
    unsigned long long p0, p1;
    asm("mov.b64 %0, {%1, %2};" : "=l"(p0) : "f"(v.x), "f"(v.y));
    asm("mov.b64 %0, {%1, %2};" : "=l"(p1) : "f"(v.z), "f"(v.w));
    asm("mul.rn.f32x2 %0, %0, %1;" : "+l"(p0) : "l"(L2E2));
    asm("mul.rn.f32x2 %0, %0, %1;" : "+l"(p1) : "l"(L2E2));
    float a, b, c, d;
    asm("mov.b64 {%0, %1}, %2;" : "=f"(a), "=f"(b) : "l"(p0));
    asm("mov.b64 {%0, %1}, %2;" : "=f"(c), "=f"(d) : "l"(p1));
    float ea, eb, ec, ed;
    asm("ex2.approx.f32 %0, %1;" : "=f"(ea) : "f"(a));
    asm("ex2.approx.f32 %0, %1;" : "=f"(eb) : "f"(b));
    asm("ex2.approx.f32 %0, %1;" : "=f"(ec) : "f"(c));
    asm("ex2.approx.f32 %0, %1;" : "=f"(ed) : "f"(d));
    return (ea + eb) + (ec + ed);
}

// Persistent CTA (2/SM), 3-stage cp.async.bulk pipeline through smem.
// (R7 structure — best measured — plus evict_first + f32x2 micro-opts.)
template <int NL>
__global__ void __launch_bounds__(BDIM, 2)
pers_kernel(const float* __restrict__ prd, const int* __restrict__ tgt,
            float* __restrict__ out, int xc, int B, int G)
{
    constexpr int ROW_BYTES = NL * 4;          // 32768
    constexpr int ROW_F4    = NL / 4;          // 2048 float4

    extern __shared__ float4 stage[];          // STAGES * ROW_F4

    __shared__ __align__(8) unsigned long long mbar_store[STAGES];
    __shared__ float sh[2][2][BDIM / 32];      // [row parity][{z,sel}][warp]
    __shared__ int   shn[2][BDIM / 32];        // [row parity][warp] hit counts
    __shared__ int   s_nl[2];
    __shared__ int   s_last;

    const int tid = threadIdx.x;
    const int w   = tid >> 5;
    const int l   = tid & 31;
    const int X   = xc - 1;
    const int bid = blockIdx.x;

    // row range for this CTA
    const int per   = B / G;
    const int rem   = B % G;
    const int start = bid * per + (bid < rem ? bid : rem);
    const int cnt   = per + (bid < rem ? 1 : 0);

    unsigned int mb[STAGES];
#pragma unroll
    for (int s = 0; s < STAGES; s++) mb[s] = smem_u32(&mbar_store[s]);

    if (tid == 0) {
#pragma unroll
        for (int s = 0; s < STAGES; s++) mbar_init(mb[s], 1);
    }
    __syncthreads();

    // initial prefetch: rows start..start+STAGES-1
    if (tid == 0) {
#pragma unroll
        for (int j = 0; j < STAGES; j++) {
            if (j < cnt) {
                mbar_expect_tx(mb[j], ROW_BYTES);
                bulk_g2s_ef(smem_u32(stage + j * ROW_F4),
                            prd + (size_t)(start + j) * NL, ROW_BYTES, mb[j]);
            }
        }
    }

    // labels for the first row (prefetched one row ahead thereafter)
    int labv = 0;
    if (tid <= X && cnt > 0) labv = tgt[(size_t)start * xc + tid];

    float acc_loss = 0.0f;   // meaningful in thread 0 only
    float acc_keep = 0.0f;

    int s = 0, ph = 0, wraps = 0;
    for (int i = 0; i < cnt; i++) {
        mbar_wait(mb[s], ph);

        // prefetch next row's labels (latency hides under exp phase)
        int labn = 0;
        if (tid <= X && (i + 1) < cnt)
            labn = tgt[(size_t)(start + i + 1) * xc + tid];

        const float4* rowp = stage + s * ROW_F4;
        const float*  rowf = (const float*)rowp;

        // exp-sum of the whole row from smem
        float lsum = 0.0f;
#pragma unroll
        for (int k = 0; k < 8; k++)
            lsum += exp_sum4(rowp[tid + k * BDIM]);

        // label gather straight from smem (row is resident)
        bool  hit = (tid < X) && (labv != 0);
        float sel = hit ? __expf(rowf[labv]) : 0.0f;
        if (tid == X) s_nl[i & 1] = labv;      // num_listed

        // per-row block reduction: 2 float warp-sums + ballot popc
        float r0 = warp_sum(lsum);
        float r1 = warp_sum(sel);
        unsigned int bal = __ballot_sync(0xffffffffu, hit);
        if (l == 0) {
            sh[i & 1][0][w] = r0;
            sh[i & 1][1][w] = r1;
            shn[i & 1][w]   = __popc(bal);
        }
        __syncthreads();   // all reads of stage s complete past this point

        // refill stage s with row i+STAGES
        if (tid == 0 && (i + STAGES) < cnt) {
            mbar_expect_tx(mb[s], ROW_BYTES);
            bulk_g2s_ef(smem_u32(stage + s * ROW_F4),
                        prd + (size_t)(start + i + STAGES) * NL, ROW_BYTES, mb[s]);
        }

        if (tid < 32) {
            const int NW = BDIM / 32;
            float z  = (tid < NW) ? sh[i & 1][0][tid] : 0.0f;
            float y  = (tid < NW) ? sh[i & 1][1][tid] : 0.0f;
            int   ni = (tid < NW) ? shn[i & 1][tid]   : 0;
            z = warp_sum(z);
            y = warp_sum(y);
#pragma unroll
            for (int o = 16; o > 0; o >>= 1)
                ni += __shfl_xor_sync(0xffffffffu, ni, o);
            if (tid == 0) {
                int num_listed = s_nl[i & 1];
                int ignored    = X - ni;
                bool keep      = (num_listed - ignored) > 0;
                if (keep) {
                    acc_loss += -__logf(y / z + 1e-5f);
                    acc_keep += 1.0f;
                }
            }
        }

        labv = labn;
        if (++s == STAGES) { s = 0; wraps ^= 1; }
        ph = wraps;
    }

    // ---- one global write per CTA, then last-CTA tiny reduce ----
    if (tid == 0) {
        g_part[bid] = make_float2(acc_loss, acc_keep);
        __threadfence();
        unsigned int n = atomicAdd(&g_done, 1u);
        s_last = (n == (unsigned int)(G - 1)) ? 1 : 0;
    }
    __syncthreads();
    if (!s_last) return;
    __threadfence();   // acquire

    float ssum = 0.0f, csum = 0.0f;
    for (int i = tid; i < G; i += BDIM) {
        float2 v = g_part[i];
        ssum += v.x;
        csum += v.y;
    }
    ssum = warp_sum(ssum);
    csum = warp_sum(csum);
    __syncthreads();
    if (l == 0) { sh[0][0][w] = ssum; sh[0][1][w] = csum; }
    __syncthreads();
    if (tid < 32) {
        float x  = (tid < BDIM / 32) ? sh[0][0][tid] : 0.0f;
        float cc = (tid < BDIM / 32) ? sh[0][1][tid] : 0.0f;
        x  = warp_sum(x);
        cc = warp_sum(cc);
        if (tid == 0) {
            out[0] = x / fmaxf(cc, 1.0f);
            g_done = 0;                      // reset for next graph replay
        }
    }
}

// Generic fallback (any nlabels).
__device__ float2 g_row_fb[65536];
__global__ void __launch_bounds__(256)
fused_generic(const float* __restrict__ prd, const int* __restrict__ tgt,
              float* __restrict__ out, int nlabels, int xc, int B)
{
    __shared__ float shf[8];
    __shared__ float shs[8];
    __shared__ float shc[8];
    __shared__ int   s_last;

    const int row = blockIdx.x;
    const int tid = threadIdx.x;
    const int w   = tid >> 5;
    const int l   = tid & 31;

    const float* p    = prd + (size_t)row * nlabels;
    const int*   trow = tgt + (size_t)row * xc;
    const int    X    = xc - 1;

    float lsum = 0.0f;
    for (int i = tid; i < nlabels; i += 256) lsum += __expf(p[i]);

    float sel = 0.0f, nzf = 0.0f;
    for (int j = tid; j < X; j += 256) {
        int lab = trow[j];
        if (lab != 0) { sel += __expf(p[lab]); nzf += 1.0f; }
    }

    float a = warp_sum(lsum), b = warp_sum(sel), c = warp_sum(nzf);
    if (l == 0) { shf[w] = a; shs[w] = b; shc[w] = c; }
    __syncthreads();
    if (tid < 32) {
        float x  = (tid < 8) ? shf[tid] : 0.0f;
        float y  = (tid < 8) ? shs[tid] : 0.0f;
        float cc = (tid < 8) ? shc[tid] : 0.0f;
        x = warp_sum(x); y = warp_sum(y); cc = warp_sum(cc);
        if (tid == 0) {
            int num_listed = trow[X];
            int ignored    = X - (int)(cc + 0.5f);
            bool keep      = (num_listed - ignored) > 0;
            float per      = -__logf(y / x + 1e-5f);
            g_row_fb[row] = make_float2(keep ? per : 0.0f, keep ? 1.0f : 0.0f);
        }
    }
    if (tid == 0) {
        __threadfence();
        unsigned int n = atomicAdd(&g_done, 1u);
        s_last = (n == (unsigned int)(gridDim.x - 1)) ? 1 : 0;
    }
    __syncthreads();
    if (!s_last) return;
    __threadfence();

    float s = 0.0f, c2 = 0.0f;
    for (int i = tid; i < B; i += 256) {
        float2 v = g_row_fb[i];
        s += v.x; c2 += v.y;
    }
    s = warp_sum(s); c2 = warp_sum(c2);
    __syncthreads();
    if (l == 0) { shf[w] = s; shs[w] = c2; }
    __syncthreads();
    if (tid < 32) {
        float x  = (tid < 8) ? shf[tid] : 0.0f;
        float cc = (tid < 8) ? shs[tid] : 0.0f;
        x = warp_sum(x); cc = warp_sum(cc);
        if (tid == 0) { out[0] = x / fmaxf(cc, 1.0f); g_done = 0; }
    }
}

extern "C" void kernel_launch(void* const* d_in, const int* in_sizes, int n_in,
                              void* d_out, int out_size)
{
    const float* prd = (const float*)d_in[0];
    const int*   tgt = (const int*)d_in[1];

    const int xc = 51;                               // X=50 labels + count col
    const int B  = in_sizes[1] / xc;
    const int nlabels = (int)((long long)in_sizes[0] / B);

    if (nlabels == 8192) {
        int sms = 148;
        cudaDeviceGetAttribute(&sms, cudaDevAttrMultiProcessorCount, 0);
        int G = 2 * sms;                             // 2 persistent CTAs per SM
        if (G > B)    G = B;
        if (G > MAXG) G = MAXG;
        size_t dyn = (size_t)STAGES * 8192 * sizeof(float);   // 96 KB per CTA
        cudaFuncSetAttribute(pers_kernel<8192>,
                             cudaFuncAttributeMaxDynamicSharedMemorySize, (int)dyn);
        pers_kernel<8192><<<G, BDIM, dyn>>>(prd, tgt, (float*)d_out, xc, B, G);
    } else {
        fused_generic<<<B, 256>>>(prd, tgt, (float*)d_out, nlabels, xc, B);
    }
}